// round 10
// baseline (speedup 1.0000x reference)
#include <cuda_runtime.h>
#include <math.h>

#define Hh 512
#define Ww 512
#define Bb 16
#define HW (Hh * Ww)
#define TOT (Bb * HW)
#define LOSS_BLOCKS_PER_B 8
#define NLOSSBLK (Bb * LOSS_BLOCKS_PER_B)

// ---------------- device scratch (static: no allocations allowed) ----------------
__device__ float         g_d[TOT];        // distance grid (pass1 out, then final)
__device__ unsigned char g_bmask[TOT];    // bit0: boundary, bit1: (tgt==0)
__device__ double        g_focal_acc, g_bnd_acc;
__device__ double        g_inter[Bb], g_sp[Bb], g_st[Bb];
__device__ float         g_dmax[Bb];
__device__ int           g_hasb[Bb], g_hasfg[Bb];

// ---------------- zero accumulators (graph replay: reset every launch) ----------------
__global__ void zero_kernel() {
    int t = threadIdx.x;
    if (t == 0) { g_focal_acc = 0.0; g_bnd_acc = 0.0; }
    if (t < Bb) {
        g_inter[t] = 0.0; g_sp[t] = 0.0; g_st[t] = 0.0;
        g_hasb[t] = 0; g_hasfg[t] = 0;
    }
}

// ---------------- boundary bits + per-sample flags ----------------
__global__ void prep_kernel(const int* __restrict__ tgt) {
    int idx = blockIdx.x * blockDim.x + threadIdx.x;   // grid sized exactly TOT
    int b   = idx / HW;
    int rem = idx - b * HW;
    int i   = rem / Ww;
    int j   = rem - i * Ww;
    const int* tb = tgt + b * HW;

    int anyFg = 0, anyBg = 0;
    #pragma unroll
    for (int di = -1; di <= 1; di++) {
        int ii = i + di;
        if (ii < 0 || ii >= Hh) continue;   // OOB contributes 0 to both maxpools
        #pragma unroll
        for (int dj = -1; dj <= 1; dj++) {
            int jj = j + dj;
            if (jj < 0 || jj >= Ww) continue;
            int v = tb[ii * Ww + jj];
            anyFg |= (v != 0);
            anyBg |= (v == 0);
        }
    }
    int boundary = anyFg & anyBg;            // dil==1 && ero==0
    int fgc      = (tb[rem] != 0);
    g_bmask[idx] = (unsigned char)(boundary | ((fgc ^ 1) << 1));

    int ab = __syncthreads_or(boundary);     // block lies fully inside one sample
    int af = __syncthreads_or(fgc);
    if (threadIdx.x == 0) {
        if (ab) atomicOr(&g_hasb[b], 1);
        if (af) atomicOr(&g_hasfg[b], 1);
    }
}

// ---------------- helpers ----------------
__device__ __forceinline__ float softplusf(float y) {
    return fmaxf(y, 0.0f) + log1pf(expf(-fabsf(y)));
}
__device__ __forceinline__ float warp_sum(float v) {
    for (int o = 16; o; o >>= 1) v += __shfl_down_sync(0xffffffffu, v, o);
    return v;
}

// Balanced tree min of 16 registers (depth 4 -> ~16 cy): feeds the warp scan early.
__device__ __forceinline__ float tree_min16(const float* v) {
    float a0 = fminf(v[0], v[1]),  a1 = fminf(v[2], v[3]);
    float a2 = fminf(v[4], v[5]),  a3 = fminf(v[6], v[7]);
    float a4 = fminf(v[8], v[9]),  a5 = fminf(v[10], v[11]);
    float a6 = fminf(v[12], v[13]), a7 = fminf(v[14], v[15]);
    float b0 = fminf(a0, a1), b1 = fminf(a2, a3);
    float b2 = fminf(a4, a5), b3 = fminf(a6, a7);
    return fminf(fminf(b0, b1), fminf(b2, b3));
}

// Two-level inclusive min-scan over 16 registers (24 ops, depth ~28 cy).
// Completes inside the warp-scan latency shadow. Min is exact under any order.
#define LOCAL_CUMMIN16(v) do {                                                     \
    v[1]=fminf(v[1],v[0]);  v[5]=fminf(v[5],v[4]);                                 \
    v[9]=fminf(v[9],v[8]);  v[13]=fminf(v[13],v[12]);                              \
    v[2]=fminf(v[2],v[1]);  v[6]=fminf(v[6],v[5]);                                 \
    v[10]=fminf(v[10],v[9]); v[14]=fminf(v[14],v[13]);                             \
    v[3]=fminf(v[3],v[2]);  v[7]=fminf(v[7],v[6]);                                 \
    v[11]=fminf(v[11],v[10]); v[15]=fminf(v[15],v[14]);                            \
    v[7]=fminf(v[7],v[3]);  v[11]=fminf(v[11],v[7]);  v[15]=fminf(v[15],v[11]);    \
    v[4]=fminf(v[4],v[3]);  v[5]=fminf(v[5],v[3]);  v[6]=fminf(v[6],v[3]);         \
    v[8]=fminf(v[8],v[7]);  v[9]=fminf(v[9],v[7]);  v[10]=fminf(v[10],v[7]);       \
    v[12]=fminf(v[12],v[11]); v[13]=fminf(v[13],v[11]); v[14]=fminf(v[14],v[11]);  \
} while (0)

// Warp exclusive min-scan of per-lane group totals (gt). BIG identity at lane 0.
__device__ __forceinline__ float warp_excl_min(float gt, int t) {
    const unsigned full = 0xffffffffu;
    float incl = gt;
    #pragma unroll
    for (int off = 1; off < 32; off <<= 1) {
        float n = __shfl_up_sync(full, incl, off);
        if (t >= off) incl = fminf(incl, n);
    }
    float excl = __shfl_up_sync(full, incl, 1);
    if (t == 0) excl = 3.0e38f;
    return excl;
}

// ---------------- chamfer warp body: 1 warp per sample, 16 cols/thread ----------
__device__ void chamfer_body(int b, int t) {
    const float A = 0.955f, Bd = 1.3693f, INF = 1e6f;
    const unsigned full = 0xffffffffu;
    float* d = g_d + b * HW;
    const unsigned char* bm = g_bmask + b * HW;
    int hasb = g_hasb[b];

    float ajv[16];
    #pragma unroll
    for (int k = 0; k < 16; k++) ajv[k] = A * (float)(16 * t + k);

    float prev[16];
    #pragma unroll
    for (int k = 0; k < 16; k++) prev[k] = INF;
    float lh = INF, rh = INF;

    // ================= pass 1: top-left -> bottom-right =================
    // depth-2 prefetch: load row i+2 while computing row i (covers L2 ~262 cy)
    uint4 raw  = *(const uint4*)(bm + 0 * Ww + t * 16);
    uint4 rn1  = *(const uint4*)(bm + 1 * Ww + t * 16);
    for (int i = 0; i < Hh; i++) {
        uint4 rn2 = rn1;
        if (i + 2 < Hh) rn2 = *(const uint4*)(bm + (i + 2) * Ww + t * 16);

        // bit-plane select once per word: hasb uniform per sample; >>1 maps
        // bit1 of each byte onto bit0 of the same byte.
        unsigned ws0 = hasb ? raw.x : (raw.x >> 1);
        unsigned ws1 = hasb ? raw.y : (raw.y >> 1);
        unsigned ws2 = hasb ? raw.z : (raw.z >> 1);
        unsigned ws3 = hasb ? raw.w : (raw.w >> 1);

        float v[16];
        #pragma unroll
        for (int k = 0; k < 16; k++) {
            unsigned w  = (k < 4) ? ws0 : (k < 8) ? ws1 : (k < 12) ? ws2 : ws3;
            unsigned sel = (w >> (8 * (k & 3))) & 1u;
            float drow  = sel ? 0.0f : INF;
            float up = prev[k] + A;
            float ul = ((k > 0)  ? prev[k - 1] : lh) + Bd;
            float ur = ((k < 15) ? prev[k + 1] : rh) + Bd;
            float m  = fminf(fminf(drow, up), fminf(ul, ur));
            v[k] = m - ajv[k];
        }
        float gt = tree_min16(v);        // feeds warp scan at depth ~16
        float excl = warp_excl_min(gt, t);
        LOCAL_CUMMIN16(v);               // hidden under scan latency

        #pragma unroll
        for (int k = 0; k < 16; k++) prev[k] = ajv[k] + fminf(v[k], excl);

        // next-iteration halos issued before stores (overlap SHFL latency)
        lh = __shfl_up_sync(full, prev[15], 1);  if (t == 0)  lh = INF;
        rh = __shfl_down_sync(full, prev[0], 1); if (t == 31) rh = INF;

        float* row = d + i * Ww + t * 16;
        #pragma unroll
        for (int q = 0; q < 4; q++)
            *(float4*)(row + 4 * q) =
                make_float4(prev[4*q], prev[4*q+1], prev[4*q+2], prev[4*q+3]);
        raw = rn1; rn1 = rn2;
    }

    // ================= pass 2: on doubly-reversed grid =================
    // Thread t owns reversed cols j' in [16t,16t+16); original j = 511 - j'.
    #pragma unroll
    for (int k = 0; k < 16; k++) prev[k] = INF;
    lh = INF; rh = INF;
    float mx = 0.0f;
    int colbase = Ww - 16 - 16 * t;                     // original col of chunk start

    float4 fc[4], f1[4];                                // depth-2 prefetch buffers
    {
        const float* r0 = d + (Hh - 1) * Ww + colbase;
        const float* r1 = d + (Hh - 2) * Ww + colbase;
        #pragma unroll
        for (int q = 0; q < 4; q++) { fc[q] = *(const float4*)(r0 + 4 * q);
                                      f1[q] = *(const float4*)(r1 + 4 * q); }
    }
    for (int ip = 0; ip < Hh; ip++) {
        int i = Hh - 1 - ip;
        float4 f2[4];
        #pragma unroll
        for (int q = 0; q < 4; q++) f2[q] = f1[q];
        if (i - 2 >= 0) {
            const float* row = d + (i - 2) * Ww + colbase;
            #pragma unroll
            for (int q = 0; q < 4; q++) f2[q] = *(const float4*)(row + 4 * q);
        }

        float dr[16];                                   // dr[k] = d[i][511-16t-k]
        #pragma unroll
        for (int q = 0; q < 4; q++) {
            dr[15 - 4*q - 0] = fc[q].x;
            dr[15 - 4*q - 1] = fc[q].y;
            dr[15 - 4*q - 2] = fc[q].z;
            dr[15 - 4*q - 3] = fc[q].w;
        }

        float v[16];
        #pragma unroll
        for (int k = 0; k < 16; k++) {
            float up = prev[k] + A;
            float ul = ((k > 0)  ? prev[k - 1] : lh) + Bd;
            float ur = ((k < 15) ? prev[k + 1] : rh) + Bd;
            float m  = fminf(fminf(dr[k], up), fminf(ul, ur));
            v[k] = m - ajv[k];
        }
        float gt = tree_min16(v);
        float excl = warp_excl_min(gt, t);
        LOCAL_CUMMIN16(v);

        #pragma unroll
        for (int k = 0; k < 16; k++) {
            float cur = ajv[k] + fminf(v[k], excl);
            prev[k] = cur;
            mx = fmaxf(mx, cur);
        }

        lh = __shfl_up_sync(full, prev[15], 1);  if (t == 0)  lh = INF;
        rh = __shfl_down_sync(full, prev[0], 1); if (t == 31) rh = INF;

        float* row = d + i * Ww + colbase;              // write back reversed
        #pragma unroll
        for (int q = 0; q < 4; q++)
            *(float4*)(row + 4 * q) =
                make_float4(prev[15-4*q-3], prev[15-4*q-2], prev[15-4*q-1], prev[15-4*q]);

        #pragma unroll
        for (int q = 0; q < 4; q++) { fc[q] = f1[q]; f1[q] = f2[q]; }
    }

    #pragma unroll
    for (int o = 16; o; o >>= 1) mx = fmaxf(mx, __shfl_down_sync(full, mx, o));
    if (t == 0) g_dmax[b] = mx;
}

// ---------------- dist-independent losses (focal / dice / iou partials) --------
__device__ void loss_nodist_body(int lb, const float* __restrict__ pred,
                                 const int* __restrict__ tgt) {
    int b = lb / LOSS_BLOCKS_PER_B;
    int blk = lb - b * LOSS_BLOCKS_PER_B;
    const float* pb = pred + b * HW;
    const int*   tb = tgt  + b * HW;

    float fs = 0.f, is = 0.f, ps = 0.f, ts = 0.f;
    for (int idx = blk * blockDim.x + threadIdx.x; idx < HW;
         idx += LOSS_BLOCKS_PER_B * blockDim.x) {
        float x  = pb[idx];
        int   ti = tb[idx];
        float p  = 1.0f / (1.0f + expf(-x));
        float bce = ti ? softplusf(-x) : softplusf(x);   // -log_sigmoid(+-x)
        float pt  = ti ? p : (1.0f - p);
        float at  = ti ? 0.25f : 0.75f;
        float omp = 1.0f - pt;
        fs += at * omp * omp * bce;
        if (ti) { is += p; ts += 1.0f; }
        ps += p;
    }

    __shared__ double acc[4];
    if (threadIdx.x < 4) acc[threadIdx.x] = 0.0;
    __syncthreads();
    fs = warp_sum(fs); is = warp_sum(is); ps = warp_sum(ps); ts = warp_sum(ts);
    if ((threadIdx.x & 31) == 0) {
        atomicAdd(&acc[0], (double)fs);
        atomicAdd(&acc[1], (double)is);
        atomicAdd(&acc[2], (double)ps);
        atomicAdd(&acc[3], (double)ts);
    }
    __syncthreads();
    if (threadIdx.x == 0) {
        atomicAdd(&g_focal_acc, acc[0]);
        atomicAdd(&g_inter[b],  acc[1]);
        atomicAdd(&g_sp[b],     acc[2]);
        atomicAdd(&g_st[b],     acc[3]);
    }
}

// ---------------- fused launch: 16 chamfer blocks + 128 loss blocks ------------
__global__ __launch_bounds__(256) void chamfer_loss_kernel(
        const float* __restrict__ pred, const int* __restrict__ tgt) {
    if (blockIdx.x < Bb) {
        if (threadIdx.x < 32) chamfer_body(blockIdx.x, threadIdx.x);
        return;                                 // no __syncthreads in this branch
    }
    loss_nodist_body(blockIdx.x - Bb, pred, tgt);
}

// ---------------- boundary loss (needs normalized dist) ----------------
__global__ void bnd_kernel(const float* __restrict__ pred, const int* __restrict__ tgt) {
    int b = blockIdx.y;
    const float* pb = pred + b * HW;
    const int*   tb = tgt  + b * HW;
    const float* db = g_d  + b * HW;
    int   hasfg = g_hasfg[b];
    float dmax  = g_dmax[b];
    bool  dodiv = dmax > 0.0f;
    float inv   = dodiv ? 1.0f / fmaxf(dmax, 1e-12f) : 1.0f;

    float bs = 0.f;
    for (int idx = blockIdx.x * blockDim.x + threadIdx.x; idx < HW;
         idx += gridDim.x * blockDim.x) {
        float x  = pb[idx];
        int   ti = tb[idx];
        float p  = 1.0f / (1.0f + expf(-x));
        float dval = db[idx];
        float dist = hasfg ? (dodiv ? dval * inv : dval) : 1.0f;
        bs += (ti ? (1.0f - p) : p) * (1.0f + dist);
    }

    __shared__ double acc;
    if (threadIdx.x == 0) acc = 0.0;
    __syncthreads();
    bs = warp_sum(bs);
    if ((threadIdx.x & 31) == 0) atomicAdd(&acc, (double)bs);
    __syncthreads();
    if (threadIdx.x == 0) atomicAdd(&g_bnd_acc, acc);
}

// ---------------- finalize: dice/iou ratios + uncertainty weighting ----------------
__global__ void final_kernel(const float* __restrict__ lv, float* __restrict__ out) {
    if (threadIdx.x != 0 || blockIdx.x != 0) return;
    double N = (double)TOT;
    double focal = g_focal_acc / N;
    double bnd   = g_bnd_acc / N;
    double dsum = 0.0, isum = 0.0;
    for (int b = 0; b < Bb; b++) {
        double inter = g_inter[b];
        double tot   = g_sp[b] + g_st[b];
        dsum += (2.0 * inter + 1e-6) / (tot + 1e-6);
        isum += (inter + 1e-6) / (tot - inter + 1e-6);
    }
    double dice = 1.0 - dsum / (double)Bb;
    double iou  = 1.0 - isum / (double)Bb;
    double l0 = lv[0], l1 = lv[1], l2 = lv[2], l3 = lv[3];
    double total = exp(-l0) * focal + l0
                 + exp(-l1) * dice  + l1
                 + exp(-l2) * bnd   + l2
                 + exp(-l3) * iou   + l3;
    out[0] = (float)total;
    out[1] = (float)focal;
    out[2] = (float)dice;
    out[3] = (float)bnd;
    out[4] = (float)iou;
}

extern "C" void kernel_launch(void* const* d_in, const int* in_sizes, int n_in,
                              void* d_out, int out_size) {
    const float* pred = (const float*)d_in[0];
    const int*   tgt  = (const int*)d_in[1];
    const float* lv   = (const float*)d_in[2];
    float* out = (float*)d_out;
    (void)in_sizes; (void)n_in; (void)out_size;

    zero_kernel<<<1, 64>>>();
    prep_kernel<<<TOT / 256, 256>>>(tgt);
    chamfer_loss_kernel<<<Bb + NLOSSBLK, 256>>>(pred, tgt);
    bnd_kernel<<<dim3(32, Bb), 256>>>(pred, tgt);
    final_kernel<<<1, 32>>>(lv, out);
}